// round 15
// baseline (speedup 1.0000x reference)
#include <cuda_runtime.h>
#include <cuda_fp16.h>
#include <cstdint>

#define DEV_INLINE __device__ __forceinline__

// Problem constants (fixed by setup_inputs)
constexpr int BB   = 32;
constexpr int T    = 256;
constexpr int E    = 512;
constexpr int HD   = 1024;
constexpr int HE   = 512;
constexpr int NSEQ = BB * T;                        // 8192
constexpr int OUT_OFF_H = BB * T * HD;              // 8388608
constexpr int OUT_OFF_C = OUT_OFF_H + 2 * BB * HD;  // +65536

// ---------------- static device scratch ----------------
// frag-ready state buffers: uint2 j = k16*128 + q*32 + col; halves j*4 + hs*2 + par
__device__ uint2 g_h0F[2][8192];          // decoder layer0 h (K=1024), h(t) in buf t&1
__device__ uint2 g_h1F[2][8192];          // decoder layer1 h
__device__ uint2 g_ehF[2][2][4096];       // encoder h [dir][parity] (K=512)
// frag-ready sequences: uint2 j = k16*32768 + q*8192 + n
__device__ uint2 g_X2F[2097152];          // decoder outputs (16MB)
__device__ uint2 g_Y0F[2097152];          // encoder layer0 outputs
__device__ float g_Z[(size_t)2 * 2048 * NSEQ];  // input projections per dir
__device__ float g_gconst[4096];          // x0 @ Wih0^T + bih0 + bhh0
__device__ float g_bsum1[4096];           // bih1 + bhh1
__device__ float g_encb[8192];            // enc bih+bhh per (layer,dir)

// barrier state (reset at end of each persistent kernel)
__device__ unsigned g_arr[128 * 32];      // per-block arrival flags (one 128B line each)
__device__ unsigned g_cnt2;               // fini counter

// ---------------- barrier primitives ----------------
DEV_INLINE unsigned ld_rlx(const unsigned* p) {
    unsigned v;
    asm volatile("ld.relaxed.gpu.b32 %0, [%1];" : "=r"(v) : "l"(p) : "memory");
    return v;
}
DEV_INLINE void fence_acq() {
    asm volatile("fence.acq_rel.gpu;" ::: "memory");
}
DEV_INLINE void st_rel(unsigned* p, unsigned v) {
    asm volatile("st.release.gpu.b32 [%0], %1;" :: "l"(p), "r"(v) : "memory");
}
DEV_INLINE unsigned atom_add(unsigned* p) {
    unsigned o;
    asm volatile("atom.acq_rel.gpu.add.u32 %0, [%1], 1;" : "=r"(o) : "l"(p) : "memory");
    return o;
}

// heater: keep the SM issuing full-rate FFMAs while waiting (defeats DVFS down-clock)
DEV_INLINE void heat(volatile unsigned* s_go, unsigned gen) {
    float x = 1.0f;
    while (*s_go < gen) {
#pragma unroll
        for (int i = 0; i < 16; i++)
            asm volatile("fma.rn.f32 %0, %0, %1, %2;" : "+f"(x) : "f"(1.000001f), "f"(1e-9f));
    }
    if (x == 2.0f) *s_go = gen;   // never true; keeps chain alive
}

// symmetric-scan grid barrier (warp-0 scan; nblk <= 32: one poll per lane).
// Polls are RELAXED; one acq_rel fence after observation gives acquire semantics.
DEV_INLINE void grid_bar(unsigned gen, int arrbase, int nblk,
                         int myblk, volatile unsigned* s_go) {
    __syncthreads();
    if (threadIdx.x < 32) {
        const int lane = threadIdx.x;
        if (lane == 0) st_rel(&g_arr[(arrbase + myblk) * 32], gen);
        for (int j = lane; j < nblk; j += 32) {
            while (ld_rlx(&g_arr[(arrbase + j) * 32]) < gen) { }
        }
        fence_acq();
        __syncwarp();
        if (lane == 0) *s_go = gen;
    } else {
        heat(s_go, gen);
    }
    __syncthreads();
}

// parallel-scan barrier for 128 blocks: threads 0..127 poll ONE line each (relaxed),
// then one acquire fence.
DEV_INLINE void grid_bar_dec(unsigned gen, int myblk, volatile unsigned* s_go) {
    __syncthreads();
    const int tid = threadIdx.x;
    if (tid < 128) {
        if (tid == 0) st_rel(&g_arr[myblk * 32], gen);
        while (ld_rlx(&g_arr[tid * 32]) < gen) { }
        fence_acq();
        asm volatile("bar.sync 1, 128;" ::: "memory");
        if (tid == 0) *s_go = gen;
    } else {
        heat(s_go, gen);
    }
    __syncthreads();
}

// last block to finish resets barrier state for the next launch/replay
DEV_INLINE void grid_fini(unsigned nblk) {
    __syncthreads();
    if (threadIdx.x == 0) {
        unsigned old = atom_add(&g_cnt2);
        if (old == nblk - 1u) {
            g_cnt2 = 0;
            for (int j = 0; j < 128; j++) g_arr[j * 32] = 0;
        }
    }
}

// ---------------- cp.async ----------------
DEV_INLINE void cp16(uint32_t dst, const void* src) {
    asm volatile("cp.async.cg.shared.global [%0], [%1], 16;" :: "r"(dst), "l"(src));
}
DEV_INLINE void cp_commit() { asm volatile("cp.async.commit_group;"); }
template <int N> DEV_INLINE void cp_wait() {
    asm volatile("cp.async.wait_group %0;" :: "n"(N));
}

// stage one 16KB chunk (1024 x 16B units) global -> smem with q-xor swizzle
DEV_INLINE void stage_chunk(uint32_t dstbase, const uint2* __restrict__ src, int tid) {
#pragma unroll
    for (int r = 0; r < 4; r++) {
        int j = r * 256 + tid;           // 0..1023
        int k16 = j >> 6;
        int q = (j >> 4) & 3;
        int col = (j & 15) * 2;
        int dcol = (col + 8 * q) & 31;
        cp16(dstbase + (uint32_t)((k16 * 128 + q * 32 + dcol) * 8), src + 2 * j);
    }
}

// ---------------- math helpers ----------------
// MUFU-based fast sigmoid / tanh (error ~1e-6; invisible at 1e-3 tolerance)
DEV_INLINE float sigf(float x) {
    float e = __expf(-x);
    return __fdividef(1.0f, 1.0f + e);
}
DEV_INLINE float tanhff(float x) {
    float e = __expf(-2.0f * x);
    return __fdividef(1.0f - e, 1.0f + e);
}

DEV_INLINE void mma_16816(float* c, uint32_t a0, uint32_t a1, uint32_t a2, uint32_t a3,
                          uint32_t b0, uint32_t b1) {
    asm volatile(
        "mma.sync.aligned.m16n8k16.row.col.f32.f16.f16.f32 "
        "{%0,%1,%2,%3}, {%4,%5,%6,%7}, {%8,%9}, {%0,%1,%2,%3};\n"
        : "+f"(c[0]), "+f"(c[1]), "+f"(c[2]), "+f"(c[3])
        : "r"(a0), "r"(a1), "r"(a2), "r"(a3), "r"(b0), "r"(b1));
}

// gemm from smem A (frag-packed, pre-offset to this chunk's 16 k-groups)
// + smem B (staged, swizzled); 16 k-iters; TWO independent MMA chains (k parity)
DEV_INLINE void gemm_sm1(const uint2* __restrict__ Ap, int rstr,
                         const uint2* __restrict__ Bs,
                         int r0, int cb, int lane, float acc[4]) {
    const int g = lane >> 2, q = lane & 3;
    const uint2* a = Ap + (size_t)(r0 + g) * 4 + q;
    const uint2* bp = Bs + q * 32 + ((cb + g + 8 * q) & 31);
    float cA[4] = {0.f, 0.f, 0.f, 0.f};
    float cB[4] = {0.f, 0.f, 0.f, 0.f};
#pragma unroll
    for (int k = 0; k < 16; k += 2) {
        uint2 aA0 = a[k * rstr * 4];
        uint2 aB0 = a[k * rstr * 4 + 32];
        uint2 bv0 = bp[k * 128];
        mma_16816(cA, aA0.x, aB0.x, aA0.y, aB0.y, bv0.x, bv0.y);
        uint2 aA1 = a[(k + 1) * rstr * 4];
        uint2 aB1 = a[(k + 1) * rstr * 4 + 32];
        uint2 bv1 = bp[(k + 1) * 128];
        mma_16816(cB, aA1.x, aB1.x, aA1.y, aB1.y, bv1.x, bv1.y);
    }
#pragma unroll
    for (int i = 0; i < 4; i++) acc[i] += cA[i] + cB[i];
}

// dual-A gemm sharing one B stream, 2 chains per accumulator
DEV_INLINE void gemm_sm2(const uint2* __restrict__ A0p, const uint2* __restrict__ A1p,
                         int rstr, const uint2* __restrict__ Bs,
                         int r0, int cb, int lane, float acc0[4], float acc1[4]) {
    const int g = lane >> 2, q = lane & 3;
    const uint2* a0 = A0p + (size_t)(r0 + g) * 4 + q;
    const uint2* a1 = A1p + (size_t)(r0 + g) * 4 + q;
    const uint2* bp = Bs + q * 32 + ((cb + g + 8 * q) & 31);
    float c0A[4] = {0.f, 0.f, 0.f, 0.f};
    float c0B[4] = {0.f, 0.f, 0.f, 0.f};
    float c1A[4] = {0.f, 0.f, 0.f, 0.f};
    float c1B[4] = {0.f, 0.f, 0.f, 0.f};
#pragma unroll
    for (int k = 0; k < 16; k += 2) {
        uint2 bv0 = bp[k * 128];
        uint2 aA0 = a0[k * rstr * 4];
        uint2 aB0 = a0[k * rstr * 4 + 32];
        mma_16816(c0A, aA0.x, aB0.x, aA0.y, aB0.y, bv0.x, bv0.y);
        uint2 aC0 = a1[k * rstr * 4];
        uint2 aD0 = a1[k * rstr * 4 + 32];
        mma_16816(c1A, aC0.x, aD0.x, aC0.y, aD0.y, bv0.x, bv0.y);
        uint2 bv1 = bp[(k + 1) * 128];
        uint2 aA1 = a0[(k + 1) * rstr * 4];
        uint2 aB1 = a0[(k + 1) * rstr * 4 + 32];
        mma_16816(c0B, aA1.x, aB1.x, aA1.y, aB1.y, bv1.x, bv1.y);
        uint2 aC1 = a1[(k + 1) * rstr * 4];
        uint2 aD1 = a1[(k + 1) * rstr * 4 + 32];
        mma_16816(c1B, aC1.x, aD1.x, aC1.y, aD1.y, bv1.x, bv1.y);
    }
#pragma unroll
    for (int i = 0; i < 4; i++) {
        acc0[i] += c0A[i] + c0B[i];
        acc1[i] += c1A[i] + c1B[i];
    }
}

// one A (pre-offset to chunk), two n-tiles (cb, cb+8) sharing A loads, 2 chains each
DEV_INLINE void gemm_sm2n(const uint2* __restrict__ Ap, int rstr,
                          const uint2* __restrict__ Bs,
                          int r0, int cb, int lane, float acc0[4], float acc1[4]) {
    const int g = lane >> 2, q = lane & 3;
    const uint2* a = Ap + (size_t)(r0 + g) * 4 + q;
    const uint2* b0p = Bs + q * 32 + ((cb + g + 8 * q) & 31);
    const uint2* b1p = Bs + q * 32 + ((cb + 8 + g + 8 * q) & 31);
    float c0A[4] = {0.f, 0.f, 0.f, 0.f};
    float c0B[4] = {0.f, 0.f, 0.f, 0.f};
    float c1A[4] = {0.f, 0.f, 0.f, 0.f};
    float c1B[4] = {0.f, 0.f, 0.f, 0.f};
#pragma unroll
    for (int k = 0; k < 16; k += 2) {
        uint2 aA0 = a[k * rstr * 4];
        uint2 aB0 = a[k * rstr * 4 + 32];
        uint2 bv00 = b0p[k * 128];
        uint2 bv10 = b1p[k * 128];
        mma_16816(c0A, aA0.x, aB0.x, aA0.y, aB0.y, bv00.x, bv00.y);
        mma_16816(c1A, aA0.x, aB0.x, aA0.y, aB0.y, bv10.x, bv10.y);
        uint2 aA1 = a[(k + 1) * rstr * 4];
        uint2 aB1 = a[(k + 1) * rstr * 4 + 32];
        uint2 bv01 = b0p[(k + 1) * 128];
        uint2 bv11 = b1p[(k + 1) * 128];
        mma_16816(c0B, aA1.x, aB1.x, aA1.y, aB1.y, bv01.x, bv01.y);
        mma_16816(c1B, aA1.x, aB1.x, aA1.y, aB1.y, bv11.x, bv11.y);
    }
#pragma unroll
    for (int i = 0; i < 4; i++) {
        acc0[i] += c0A[i] + c0B[i];
        acc1[i] += c1A[i] + c1B[i];
    }
}

// global-B gemm (for k_z only; bulk, latency-tolerant), 2 chains
DEV_INLINE void gemm_g(const uint2* __restrict__ Au, int rstr, int K16,
                       const uint2* __restrict__ Bf, int nstr, int r0,
                       int colbase, int lane, float acc[4]) {
    const int g = lane >> 2, q = lane & 3;
    const uint2* ap = Au + (size_t)(r0 + g) * 4 + q;
    const uint2* bp = Bf + (size_t)q * nstr + colbase + g;
    float cA[4] = {0.f, 0.f, 0.f, 0.f};
    float cB[4] = {0.f, 0.f, 0.f, 0.f};
#pragma unroll 4
    for (int k = 0; k < K16; k += 2) {
        uint2 aA0 = ap[(size_t)k * rstr * 4];
        uint2 aB0 = ap[(size_t)k * rstr * 4 + 32];
        uint2 bv0 = bp[(size_t)k * 4 * nstr];
        mma_16816(cA, aA0.x, aB0.x, aA0.y, aB0.y, bv0.x, bv0.y);
        uint2 aA1 = ap[(size_t)(k + 1) * rstr * 4];
        uint2 aB1 = ap[(size_t)(k + 1) * rstr * 4 + 32];
        uint2 bv1 = bp[(size_t)(k + 1) * 4 * nstr];
        mma_16816(cB, aA1.x, aB1.x, aA1.y, aB1.y, bv1.x, bv1.y);
    }
#pragma unroll
    for (int i = 0; i < 4; i++) acc[i] += cA[i] + cB[i];
}

DEV_INLINE void frag_st(float* gsm, int r0, int colbase, int lane, const float acc[4]) {
    const int g = lane >> 2, q = lane & 3;
    float* p = gsm + (r0 + g) * 33 + colbase + 2 * q;
    p[0] = acc[0]; p[1] = acc[1];
    p[8 * 33] = acc[2]; p[8 * 33 + 1] = acc[3];
}

// pack 4 consecutive source cols (c % 4 == 0) of row s into frag-packed smem layout
DEV_INLINE void pack4(__half* A, int rows, int s, int c, float4 v) {
    int k16 = c >> 4, hi = (c >> 3) & 1, q = (c >> 1) & 3;
    __half* p = A + (((size_t)(k16 * rows + s)) << 4) + q * 4 + hi * 2;
    p[0] = __float2half(v.x); p[1] = __float2half(v.y);
    p[4] = __float2half(v.z); p[5] = __float2half(v.w);
}

// state-buffer half index for feature f, batch b
DEV_INLINE int st_hidx(int f, int b) {
    int kr = f >> 1;
    return (kr >> 3) * 512 + (kr & 3) * 128 + b * 4 + (((kr >> 2) & 1) << 1) + (f & 1);
}
// sequence-buffer half base for feature f (add n*4)
DEV_INLINE int seq_base(int f) {
    int kr = f >> 1;
    return (kr >> 3) * 131072 + (kr & 3) * 32768 + (((kr >> 2) & 1) << 1) + (f & 1);
}

// ---------------- setup ----------------
__global__ void k_setup(const float* __restrict__ emb, const float* __restrict__ Wih0,
                        const float* __restrict__ bih0, const float* __restrict__ bhh0,
                        const float* __restrict__ bih1, const float* __restrict__ bhh1,
                        const float* __restrict__ ebih, const float* __restrict__ ebhh) {
    int j = blockIdx.x * blockDim.x + threadIdx.x;
    if (j < 4096) {
        const float4* xr = (const float4*)(emb + E);               // BOS row
        const float4* wr = (const float4*)(Wih0 + (size_t)j * E);
        float s = 0.f;
#pragma unroll 4
        for (int k = 0; k < E / 4; k++) {
            float4 a = xr[k], w = wr[k];
            s += a.x * w.x + a.y * w.y + a.z * w.z + a.w * w.w;
        }
        g_gconst[j] = s + bih0[j] + bhh0[j];
        g_bsum1[j] = bih1[j] + bhh1[j];
    }
    if (j < 8192) g_encb[j] = ebih[j] + ebhh[j];
}

// ---------------- persistent decoder ----------------
// 128 blocks x 256 threads; block owns units [blk*8, blk*8+8) x 4 gates, both layers.
// interval k: layer0 computes h0(k) (k<T); layer1 computes h1(k-1) (k>=1).
__global__ void __launch_bounds__(256, 1) k_dec(const float* __restrict__ Whh0,
                                                const float* __restrict__ Wih1,
                                                const float* __restrict__ Whh1,
                                                const float* __restrict__ enc_h,
                                                const float* __restrict__ enc_c) {
    extern __shared__ __half sm[];
    __half* A0 = sm;                              // 32 x 1024 frag-packed (64KB each)
    __half* A1 = sm + 32768;
    __half* A2 = sm + 65536;
    __half* STG = sm + 98304;                     // 2 x 16KB staging
    float* gsm0 = (float*)STG;                    // aliases staging buffer 0
    float* gsm1 = gsm0 + 1056;
    volatile unsigned* s_go = (volatile unsigned*)(sm + 114688);  // past STG
    const uint32_t stg_b = (uint32_t)__cvta_generic_to_shared(STG);
    const int tid = threadIdx.x, lane = tid & 31, w = tid >> 5;
    const int u0 = blockIdx.x * 8;

    if (tid == 0) *s_go = 0;

    for (int i = tid; i < 8192; i += 256) {
        int s = i >> 8;
        int c = (i & 255) * 4;
        size_t grow = (size_t)((s >> 3) * 1024 + u0 + (s & 7));
        pack4(A0, 32, s, c, *(const float4*)(Whh0 + grow * 1024 + c));
        pack4(A1, 32, s, c, *(const float4*)(Wih1 + grow * 1024 + c));
        pack4(A2, 32, s, c, *(const float4*)(Whh1 + grow * 1024 + c));
    }

    const int u = w, b = lane, uu = u0 + u;
    const int hp = st_hidx(uu, b);
    const int xb = seq_base(uu);
    float c0 = enc_c[b * 1024 + uu];
    float c1 = enc_c[32768 + b * 1024 + uu];
    ((__half*)g_h0F[1])[hp] = __float2half(enc_h[b * 1024 + uu]);   // h(-1) -> buf 1
    ((__half*)g_h1F[1])[hp] = __float2half(enc_h[32768 + b * 1024 + uu]);
    const float gci = g_gconst[uu],        gcf = g_gconst[1024 + uu];
    const float gcg = g_gconst[2048 + uu], gco = g_gconst[3072 + uu];
    const float b1i = g_bsum1[uu],         b1f = g_bsum1[1024 + uu];
    const float b1g = g_bsum1[2048 + uu],  b1o = g_bsum1[3072 + uu];
    const int mt = w & 1, ntc = (w >> 1) * 8, r0 = mt * 16;
    const uint2* Au0 = (const uint2*)A0;
    const uint2* Au1 = (const uint2*)A1;
    const uint2* Au2 = (const uint2*)A2;

    grid_bar_dec(1, blockIdx.x, s_go);

    for (int k = 0; k <= T; k++) {
        const int pk = k & 1, pm1 = pk ^ 1;
        float a0c[4] = {0.f, 0.f, 0.f, 0.f};
        float a1c[4] = {0.f, 0.f, 0.f, 0.f};
        const uint2* h0src = g_h0F[pm1];
        const uint2* h1src = g_h1F[pk];
        const int cend = (k == 0) ? 4 : 8;

        stage_chunk(stg_b, h0src, tid); cp_commit();
        for (int c = 0; c < cend; c++) {
            __syncthreads();
            if (c + 1 < cend) {
                const uint2* nsrc = (c + 1 < 4) ? h0src + (c + 1) * 2048
                                                : h1src + (c - 3) * 2048;
                stage_chunk(stg_b + ((c + 1) & 1) * 16384u, nsrc, tid);
                cp_commit();
                cp_wait<1>();
            } else {
                cp_wait<0>();
            }
            __syncthreads();
            const uint2* Bs = (const uint2*)(STG) + (c & 1) * 2048;
            if (c < 4) {
                // A offset for this chunk's 16 k-groups: c * 16 * (rstr*4=128) = c*2048
                const uint2* A0c = Au0 + (size_t)c * 2048;
                const uint2* A1c = Au1 + (size_t)c * 2048;
                if (k == 0)       gemm_sm1(A0c, 32, Bs, r0, ntc, lane, a0c);
                else if (k == T)  gemm_sm1(A1c, 32, Bs, r0, ntc, lane, a1c);
                else              gemm_sm2(A0c, A1c, 32, Bs, r0, ntc, lane, a0c, a1c);
            } else {
                const uint2* A2c = Au2 + (size_t)(c - 4) * 2048;
                gemm_sm1(A2c, 32, Bs, r0, ntc, lane, a1c);
            }
        }
        // no sync needed: gsm aliases staging buffer 0; final chunk GEMM (odd) read
        // buffer 1, and no cp.async targets buffer 0 here. frag_st slots warp-private.
        if (k < T)  frag_st(gsm0, r0, ntc, lane, a0c);
        if (k >= 1) frag_st(gsm1, r0, ntc, lane, a1c);
        __syncthreads();
        if (k < T) {
            float iv = gsm0[u * 33 + b] + gci;
            float fv = gsm0[(8 + u) * 33 + b] + gcf;
            float gv = gsm0[(16 + u) * 33 + b] + gcg;
            float ov = gsm0[(24 + u) * 33 + b] + gco;
            c0 = sigf(fv) * c0 + sigf(iv) * tanhff(gv);
            float h = sigf(ov) * tanhff(c0);
            ((__half*)g_h0F[pk])[hp] = __float2half(h);   // h0(k)
        }
        if (k >= 1) {
            float iv = gsm1[u * 33 + b] + b1i;
            float fv = gsm1[(8 + u) * 33 + b] + b1f;
            float gv = gsm1[(16 + u) * 33 + b] + b1g;
            float ov = gsm1[(24 + u) * 33 + b] + b1o;
            c1 = sigf(fv) * c1 + sigf(iv) * tanhff(gv);
            float h = sigf(ov) * tanhff(c1);
            __half hh = __float2half(h);
            ((__half*)g_h1F[pm1])[hp] = hh;               // h1(k-1)
            ((__half*)g_X2F)[xb + ((k - 1) * 32 + b) * 4] = hh;
        }
        grid_bar_dec(2 + k, blockIdx.x, s_go);
    }
    grid_fini(128);
}

// ---------------- encoder input-projection GEMM: Z = X @ Wih^T + bias ----------------
// grid (32 j-blocks, 16 n-blocks of 512, 2 dirs): weight tile reused over 512 cols.
__global__ void __launch_bounds__(256, 1) k_z(int l, const float* __restrict__ eWih) {
    extern __shared__ __half sm[];
    __half* As = sm;   // 64 x 1024 frag-packed (128KB)
    const int tid = threadIdx.x, lane = tid & 31, w = tid >> 5;
    const int jb = blockIdx.x * 64;
    const int n0 = blockIdx.y * 512;
    const int d = blockIdx.z;
    for (int i = tid; i < 16384; i += 256) {
        int s = i >> 8;
        int c = (i & 255) * 4;
        size_t grow = (size_t)(l * 2 + d) * 2048 + jb + s;
        pack4(As, 64, s, c, *(const float4*)(eWih + grow * 1024 + c));
    }
    __syncthreads();
    const uint2* Bf = l ? g_Y0F : g_X2F;
    const uint2* Au = (const uint2*)As;
    const int mt = w & 3;
    const int nh = (w >> 2) * 8;
    const int g = lane >> 2, q = lane & 3;
    float* Zp = g_Z + (size_t)d * 2048 * NSEQ;
    const float bias0 = g_encb[(l * 2 + d) * 2048 + jb + mt * 16 + g];
    const float bias1 = g_encb[(l * 2 + d) * 2048 + jb + mt * 16 + 8 + g];
    const int j0 = jb + mt * 16 + g;
    for (int ch = 0; ch < 32; ch++) {
        float acc[4] = {0.f, 0.f, 0.f, 0.f};
        gemm_g(Au, 64, 64, Bf, 8192, mt * 16, n0 + ch * 16 + nh, lane, acc);
        int n = n0 + ch * 16 + nh + 2 * q;
        Zp[(size_t)j0 * NSEQ + n]           = acc[0] + bias0;
        Zp[(size_t)j0 * NSEQ + n + 1]       = acc[1] + bias0;
        Zp[(size_t)(j0 + 8) * NSEQ + n]     = acc[2] + bias1;
        Zp[(size_t)(j0 + 8) * NSEQ + n + 1] = acc[3] + bias1;
    }
}

// ---------------- persistent encoder (64 blocks: 2 dirs x 32 blocks x 16 units) ------
// fwd and bwd use INDEPENDENT barrier domains; single-shot staging of the 32KB state;
// gsm in a DEDICATED smem region.
__global__ void __launch_bounds__(256, 1) k_enc(int l, const float* __restrict__ eWhh,
                                                float* __restrict__ out) {
    extern __shared__ __half sm[];
    __half* As = sm;                      // 64 x 512 frag-packed (64KB)
    __half* STG = sm + 32768;             // 2 x 16KB staging (whole state, one shot)
    float* gsm = (float*)(sm + 49152);    // dedicated 64 x 33 floats (8448B)
    volatile unsigned* s_go = (volatile unsigned*)(sm + 53376);
    const uint32_t stg_b = (uint32_t)__cvta_generic_to_shared(STG);
    const int tid = threadIdx.x, lane = tid & 31, w = tid >> 5;
    const int d = blockIdx.x >> 5;
    const int myblk = blockIdx.x & 31;
    const int u0 = myblk * 16;

    if (tid == 0) *s_go = 0;

    for (int i = tid; i < 8192; i += 256) {
        int s = i >> 7;            // 0..63 packed row: gate*16 + ulocal
        int c = (i & 127) * 4;
        size_t grow = (size_t)(l * 2 + d) * 2048 + (s >> 4) * 512 + u0 + (s & 15);
        pack4(As, 64, s, c, *(const float4*)(eWhh + grow * 512 + c));
    }

    const int mt = w & 3, r0 = mt * 16;
    const int nh = (w >> 2) * 16;
    float cst[2] = {0.f, 0.f};
    const float* Zp = g_Z + (size_t)d * 2048 * NSEQ;
    const uint2* Au = (const uint2*)As;
    __syncthreads();

    for (int s = 0; s < T; s++) {
        const int p = s & 1;
        const int tau = d ? (T - 1 - s) : s;
        // issue state staging FIRST (fire-and-forget), so it overlaps Z prefetch
        if (s) {
            const uint2* hsrc = g_ehF[d][1 - p];
            stage_chunk(stg_b, hsrc, tid);
            stage_chunk(stg_b + 16384u, hsrc + 2048, tid);
            cp_commit();
        }
        // prefetch Z for this thread's two (u,b) pairs (overlaps the cp.async burst)
        float z[2][4];
#pragma unroll
        for (int e = 0; e < 2; e++) {
            int idx = e * 256 + tid;
            int uu2 = u0 + (idx >> 5), b2 = idx & 31;
            int n2 = tau * 32 + b2;
            z[e][0] = Zp[(size_t)uu2 * NSEQ + n2];
            z[e][1] = Zp[(size_t)(512 + uu2) * NSEQ + n2];
            z[e][2] = Zp[(size_t)(1024 + uu2) * NSEQ + n2];
            z[e][3] = Zp[(size_t)(1536 + uu2) * NSEQ + n2];
        }
        float acc0[4] = {0.f, 0.f, 0.f, 0.f};
        float acc1[4] = {0.f, 0.f, 0.f, 0.f};
        if (s) {
            cp_wait<0>();
            __syncthreads();
            const uint2* Bs = (const uint2*)STG;
            gemm_sm2n(Au,        64, Bs,        r0, nh, lane, acc0, acc1);
            gemm_sm2n(Au + 4096, 64, Bs + 2048, r0, nh, lane, acc0, acc1);
        }
        // gsm is dedicated: frag_st can proceed without a pre-sync
        frag_st(gsm, r0, nh, lane, acc0);
        frag_st(gsm, r0, nh + 8, lane, acc1);
        __syncthreads();
#pragma unroll
        for (int e = 0; e < 2; e++) {
            int idx = e * 256 + tid;
            int ul = idx >> 5, b2 = idx & 31;
            int uu2 = u0 + ul;
            int n2 = tau * 32 + b2;
            float iv = gsm[ul * 33 + b2] + z[e][0];
            float fv = gsm[(16 + ul) * 33 + b2] + z[e][1];
            float gv = gsm[(32 + ul) * 33 + b2] + z[e][2];
            float ov = gsm[(48 + ul) * 33 + b2] + z[e][3];
            cst[e] = sigf(fv) * cst[e] + sigf(iv) * tanhff(gv);
            float h = sigf(ov) * tanhff(cst[e]);
            __half hh = __float2half(h);
            ((__half*)g_ehF[d][p])[st_hidx(uu2, b2)] = hh;   // h(s)
            int f = d * 512 + uu2;
            if (l == 0) {
                ((__half*)g_Y0F)[seq_base(f) + n2 * 4] = hh;
            } else {
                out[(size_t)b2 * (T * HD) + (size_t)tau * HD + f] = h;
                if (s == T - 1) {
                    out[OUT_OFF_H + b2 * HD + f] = h;
                    out[OUT_OFF_H + 32768 + b2 * HD + f] = h;
                    out[OUT_OFF_C + b2 * HD + f] = cst[e];
                    out[OUT_OFF_C + 32768 + b2 * HD + f] = cst[e];
                }
            }
        }
        grid_bar(s + 1, d * 32, 32, myblk, s_go);
    }
    grid_fini(64);
}

// ---------------- host launcher ----------------
extern "C" void kernel_launch(void* const* d_in, const int* in_sizes, int n_in,
                              void* d_out, int out_size) {
    (void)in_sizes; (void)n_in; (void)out_size;
    const float* enc_h = (const float*)d_in[1];
    const float* enc_c = (const float*)d_in[2];
    const float* emb   = (const float*)d_in[4];
    const float* Wih0  = (const float*)d_in[5];
    const float* Whh0  = (const float*)d_in[6];
    const float* bih0  = (const float*)d_in[7];
    const float* bhh0  = (const float*)d_in[8];
    const float* Wih1  = (const float*)d_in[9];
    const float* Whh1  = (const float*)d_in[10];
    const float* bih1  = (const float*)d_in[11];
    const float* bhh1  = (const float*)d_in[12];
    const float* eWih  = (const float*)d_in[13];
    const float* eWhh  = (const float*)d_in[14];
    const float* ebih  = (const float*)d_in[15];
    const float* ebhh  = (const float*)d_in[16];
    float* out = (float*)d_out;

    cudaFuncSetAttribute(k_dec, cudaFuncAttributeMaxDynamicSharedMemorySize, 229504);
    cudaFuncSetAttribute(k_z,   cudaFuncAttributeMaxDynamicSharedMemorySize, 131072);
    cudaFuncSetAttribute(k_enc, cudaFuncAttributeMaxDynamicSharedMemorySize, 107008);

    k_setup<<<32, 256>>>(emb, Wih0, bih0, bhh0, bih1, bhh1, ebih, ebhh);
    k_dec<<<128, 256, 229504>>>(Whh0, Wih1, Whh1, enc_h, enc_c);
    for (int l = 0; l < 2; l++) {
        k_z<<<dim3(32, 16, 2), 256, 131072>>>(l, eWih);
        k_enc<<<64, 256, 107008>>>(l, eWhh, out);
    }
}

// round 17
// speedup vs baseline: 1.0254x; 1.0254x over previous
#include <cuda_runtime.h>
#include <cuda_fp16.h>
#include <cstdint>

#define DEV_INLINE __device__ __forceinline__

// Problem constants (fixed by setup_inputs)
constexpr int BB   = 32;
constexpr int T    = 256;
constexpr int E    = 512;
constexpr int HD   = 1024;
constexpr int HE   = 512;
constexpr int NSEQ = BB * T;                        // 8192
constexpr int OUT_OFF_H = BB * T * HD;              // 8388608
constexpr int OUT_OFF_C = OUT_OFF_H + 2 * BB * HD;  // +65536

// ---------------- static device scratch ----------------
// frag-ready state buffers: uint2 j = k16*128 + q*32 + col; halves j*4 + hs*2 + par
__device__ uint2 g_h0F[2][8192];          // decoder layer0 h (K=1024), h(t) in buf t&1
__device__ uint2 g_h1F[2][8192];          // decoder layer1 h
__device__ uint2 g_ehF[2][2][4096];       // encoder h [dir][parity] (K=512)
// frag-ready sequences: uint2 j = k16*32768 + q*8192 + n
__device__ uint2 g_X2F[2097152];          // decoder outputs (16MB)
__device__ uint2 g_Y0F[2097152];          // encoder layer0 outputs
__device__ float g_Z[(size_t)2 * 2048 * NSEQ];  // input projections per dir
__device__ float g_gconst[4096];          // x0 @ Wih0^T + bih0 + bhh0
__device__ float g_bsum1[4096];           // bih1 + bhh1
__device__ float g_encb[8192];            // enc bih+bhh per (layer,dir)

// barrier state (reset at end of each persistent kernel)
__device__ unsigned g_arr[128 * 32];      // per-block arrival flags (one 128B line each)
__device__ unsigned g_cnt2;               // fini counter

// ---------------- barrier primitives ----------------
DEV_INLINE unsigned ld_acq(const unsigned* p) {
    unsigned v;
    asm volatile("ld.acquire.gpu.b32 %0, [%1];" : "=r"(v) : "l"(p) : "memory");
    return v;
}
DEV_INLINE void st_rel(unsigned* p, unsigned v) {
    asm volatile("st.release.gpu.b32 [%0], %1;" :: "l"(p), "r"(v) : "memory");
}
DEV_INLINE unsigned atom_add(unsigned* p) {
    unsigned o;
    asm volatile("atom.acq_rel.gpu.add.u32 %0, [%1], 1;" : "=r"(o) : "l"(p) : "memory");
    return o;
}

// heater: keep the SM issuing full-rate FFMAs while waiting (defeats DVFS down-clock)
DEV_INLINE void heat(volatile unsigned* s_go, unsigned gen) {
    float x = 1.0f;
    while (*s_go < gen) {
#pragma unroll
        for (int i = 0; i < 32; i++)
            asm volatile("fma.rn.f32 %0, %0, %1, %2;" : "+f"(x) : "f"(1.000001f), "f"(1e-9f));
    }
    if (x == 2.0f) *s_go = gen;   // never true; keeps chain alive
}

// symmetric-scan grid barrier (warp-0 scan; nblk <= 32: one poll per lane)
DEV_INLINE void grid_bar(unsigned gen, int arrbase, int nblk,
                         int myblk, volatile unsigned* s_go) {
    __syncthreads();
    if (threadIdx.x < 32) {
        const int lane = threadIdx.x;
        if (lane == 0) st_rel(&g_arr[(arrbase + myblk) * 32], gen);
        for (int j = lane; j < nblk; j += 32) {
            while (ld_acq(&g_arr[(arrbase + j) * 32]) < gen) { }
        }
        __syncwarp();
        if (lane == 0) *s_go = gen;
    } else {
        heat(s_go, gen);
    }
    __syncthreads();
}

// parallel-scan barrier for 128 blocks: threads 0..127 poll ONE line each
DEV_INLINE void grid_bar_dec(unsigned gen, int myblk, volatile unsigned* s_go) {
    __syncthreads();
    const int tid = threadIdx.x;
    if (tid < 128) {
        if (tid == 0) st_rel(&g_arr[myblk * 32], gen);
        while (ld_acq(&g_arr[tid * 32]) < gen) { }
        asm volatile("bar.sync 1, 128;" ::: "memory");
        if (tid == 0) *s_go = gen;
    } else {
        heat(s_go, gen);
    }
    __syncthreads();
}

// last block to finish resets barrier state for the next launch/replay
DEV_INLINE void grid_fini(unsigned nblk) {
    __syncthreads();
    if (threadIdx.x == 0) {
        unsigned old = atom_add(&g_cnt2);
        if (old == nblk - 1u) {
            g_cnt2 = 0;
            for (int j = 0; j < 128; j++) g_arr[j * 32] = 0;
        }
    }
}

// ---------------- cp.async ----------------
DEV_INLINE void cp16(uint32_t dst, const void* src) {
    asm volatile("cp.async.cg.shared.global [%0], [%1], 16;" :: "r"(dst), "l"(src));
}
DEV_INLINE void cp_commit() { asm volatile("cp.async.commit_group;"); }
template <int N> DEV_INLINE void cp_wait() {
    asm volatile("cp.async.wait_group %0;" :: "n"(N));
}

// stage one 16KB chunk (1024 x 16B units) global -> smem with q-xor swizzle
DEV_INLINE void stage_chunk(uint32_t dstbase, const uint2* __restrict__ src, int tid) {
#pragma unroll
    for (int r = 0; r < 4; r++) {
        int j = r * 256 + tid;           // 0..1023
        int k16 = j >> 6;
        int q = (j >> 4) & 3;
        int col = (j & 15) * 2;
        int dcol = (col + 8 * q) & 31;
        cp16(dstbase + (uint32_t)((k16 * 128 + q * 32 + dcol) * 8), src + 2 * j);
    }
}

// ---------------- math helpers ----------------
// MUFU-based fast sigmoid / tanh (error ~1e-6; invisible at 1e-3 tolerance)
DEV_INLINE float sigf(float x) {
    float e = __expf(-x);
    return __fdividef(1.0f, 1.0f + e);
}
DEV_INLINE float tanhff(float x) {
    float e = __expf(-2.0f * x);
    return __fdividef(1.0f - e, 1.0f + e);
}

DEV_INLINE void mma_16816(float* c, uint32_t a0, uint32_t a1, uint32_t a2, uint32_t a3,
                          uint32_t b0, uint32_t b1) {
    asm volatile(
        "mma.sync.aligned.m16n8k16.row.col.f32.f16.f16.f32 "
        "{%0,%1,%2,%3}, {%4,%5,%6,%7}, {%8,%9}, {%0,%1,%2,%3};\n"
        : "+f"(c[0]), "+f"(c[1]), "+f"(c[2]), "+f"(c[3])
        : "r"(a0), "r"(a1), "r"(a2), "r"(a3), "r"(b0), "r"(b1));
}

// gemm from smem A (frag-packed, pre-offset to this chunk's 16 k-groups)
// + smem B (staged, swizzled); 16 k-iters; TWO independent MMA chains (k parity)
DEV_INLINE void gemm_sm1(const uint2* __restrict__ Ap, int rstr,
                         const uint2* __restrict__ Bs,
                         int r0, int cb, int lane, float acc[4]) {
    const int g = lane >> 2, q = lane & 3;
    const uint2* a = Ap + (size_t)(r0 + g) * 4 + q;
    const uint2* bp = Bs + q * 32 + ((cb + g + 8 * q) & 31);
    float cA[4] = {0.f, 0.f, 0.f, 0.f};
    float cB[4] = {0.f, 0.f, 0.f, 0.f};
#pragma unroll
    for (int k = 0; k < 16; k += 2) {
        uint2 aA0 = a[k * rstr * 4];
        uint2 aB0 = a[k * rstr * 4 + 32];
        uint2 bv0 = bp[k * 128];
        mma_16816(cA, aA0.x, aB0.x, aA0.y, aB0.y, bv0.x, bv0.y);
        uint2 aA1 = a[(k + 1) * rstr * 4];
        uint2 aB1 = a[(k + 1) * rstr * 4 + 32];
        uint2 bv1 = bp[(k + 1) * 128];
        mma_16816(cB, aA1.x, aB1.x, aA1.y, aB1.y, bv1.x, bv1.y);
    }
#pragma unroll
    for (int i = 0; i < 4; i++) acc[i] += cA[i] + cB[i];
}

// dual-A gemm sharing one B stream, 2 chains per accumulator
DEV_INLINE void gemm_sm2(const uint2* __restrict__ A0p, const uint2* __restrict__ A1p,
                         int rstr, const uint2* __restrict__ Bs,
                         int r0, int cb, int lane, float acc0[4], float acc1[4]) {
    const int g = lane >> 2, q = lane & 3;
    const uint2* a0 = A0p + (size_t)(r0 + g) * 4 + q;
    const uint2* a1 = A1p + (size_t)(r0 + g) * 4 + q;
    const uint2* bp = Bs + q * 32 + ((cb + g + 8 * q) & 31);
    float c0A[4] = {0.f, 0.f, 0.f, 0.f};
    float c0B[4] = {0.f, 0.f, 0.f, 0.f};
    float c1A[4] = {0.f, 0.f, 0.f, 0.f};
    float c1B[4] = {0.f, 0.f, 0.f, 0.f};
#pragma unroll
    for (int k = 0; k < 16; k += 2) {
        uint2 bv0 = bp[k * 128];
        uint2 aA0 = a0[k * rstr * 4];
        uint2 aB0 = a0[k * rstr * 4 + 32];
        mma_16816(c0A, aA0.x, aB0.x, aA0.y, aB0.y, bv0.x, bv0.y);
        uint2 aC0 = a1[k * rstr * 4];
        uint2 aD0 = a1[k * rstr * 4 + 32];
        mma_16816(c1A, aC0.x, aD0.x, aC0.y, aD0.y, bv0.x, bv0.y);
        uint2 bv1 = bp[(k + 1) * 128];
        uint2 aA1 = a0[(k + 1) * rstr * 4];
        uint2 aB1 = a0[(k + 1) * rstr * 4 + 32];
        mma_16816(c0B, aA1.x, aB1.x, aA1.y, aB1.y, bv1.x, bv1.y);
        uint2 aC1 = a1[(k + 1) * rstr * 4];
        uint2 aD1 = a1[(k + 1) * rstr * 4 + 32];
        mma_16816(c1B, aC1.x, aD1.x, aC1.y, aD1.y, bv1.x, bv1.y);
    }
#pragma unroll
    for (int i = 0; i < 4; i++) {
        acc0[i] += c0A[i] + c0B[i];
        acc1[i] += c1A[i] + c1B[i];
    }
}

// one A (pre-offset to chunk), two n-tiles (cb, cb+8) sharing A loads, 2 chains each
DEV_INLINE void gemm_sm2n(const uint2* __restrict__ Ap, int rstr,
                          const uint2* __restrict__ Bs,
                          int r0, int cb, int lane, float acc0[4], float acc1[4]) {
    const int g = lane >> 2, q = lane & 3;
    const uint2* a = Ap + (size_t)(r0 + g) * 4 + q;
    const uint2* b0p = Bs + q * 32 + ((cb + g + 8 * q) & 31);
    const uint2* b1p = Bs + q * 32 + ((cb + 8 + g + 8 * q) & 31);
    float c0A[4] = {0.f, 0.f, 0.f, 0.f};
    float c0B[4] = {0.f, 0.f, 0.f, 0.f};
    float c1A[4] = {0.f, 0.f, 0.f, 0.f};
    float c1B[4] = {0.f, 0.f, 0.f, 0.f};
#pragma unroll
    for (int k = 0; k < 16; k += 2) {
        uint2 aA0 = a[k * rstr * 4];
        uint2 aB0 = a[k * rstr * 4 + 32];
        uint2 bv00 = b0p[k * 128];
        uint2 bv10 = b1p[k * 128];
        mma_16816(c0A, aA0.x, aB0.x, aA0.y, aB0.y, bv00.x, bv00.y);
        mma_16816(c1A, aA0.x, aB0.x, aA0.y, aB0.y, bv10.x, bv10.y);
        uint2 aA1 = a[(k + 1) * rstr * 4];
        uint2 aB1 = a[(k + 1) * rstr * 4 + 32];
        uint2 bv01 = b0p[(k + 1) * 128];
        uint2 bv11 = b1p[(k + 1) * 128];
        mma_16816(c0B, aA1.x, aB1.x, aA1.y, aB1.y, bv01.x, bv01.y);
        mma_16816(c1B, aA1.x, aB1.x, aA1.y, aB1.y, bv11.x, bv11.y);
    }
#pragma unroll
    for (int i = 0; i < 4; i++) {
        acc0[i] += c0A[i] + c0B[i];
        acc1[i] += c1A[i] + c1B[i];
    }
}

// global-B gemm (for k_z only; bulk, latency-tolerant), 2 chains
DEV_INLINE void gemm_g(const uint2* __restrict__ Au, int rstr, int K16,
                       const uint2* __restrict__ Bf, int nstr, int r0,
                       int colbase, int lane, float acc[4]) {
    const int g = lane >> 2, q = lane & 3;
    const uint2* ap = Au + (size_t)(r0 + g) * 4 + q;
    const uint2* bp = Bf + (size_t)q * nstr + colbase + g;
    float cA[4] = {0.f, 0.f, 0.f, 0.f};
    float cB[4] = {0.f, 0.f, 0.f, 0.f};
#pragma unroll 4
    for (int k = 0; k < K16; k += 2) {
        uint2 aA0 = ap[(size_t)k * rstr * 4];
        uint2 aB0 = ap[(size_t)k * rstr * 4 + 32];
        uint2 bv0 = bp[(size_t)k * 4 * nstr];
        mma_16816(cA, aA0.x, aB0.x, aA0.y, aB0.y, bv0.x, bv0.y);
        uint2 aA1 = ap[(size_t)(k + 1) * rstr * 4];
        uint2 aB1 = ap[(size_t)(k + 1) * rstr * 4 + 32];
        uint2 bv1 = bp[(size_t)(k + 1) * 4 * nstr];
        mma_16816(cB, aA1.x, aB1.x, aA1.y, aB1.y, bv1.x, bv1.y);
    }
#pragma unroll
    for (int i = 0; i < 4; i++) acc[i] += cA[i] + cB[i];
}

DEV_INLINE void frag_st(float* gsm, int r0, int colbase, int lane, const float acc[4]) {
    const int g = lane >> 2, q = lane & 3;
    float* p = gsm + (r0 + g) * 33 + colbase + 2 * q;
    p[0] = acc[0]; p[1] = acc[1];
    p[8 * 33] = acc[2]; p[8 * 33 + 1] = acc[3];
}

// pack 4 consecutive source cols (c % 4 == 0) of row s into frag-packed smem layout
DEV_INLINE void pack4(__half* A, int rows, int s, int c, float4 v) {
    int k16 = c >> 4, hi = (c >> 3) & 1, q = (c >> 1) & 3;
    __half* p = A + (((size_t)(k16 * rows + s)) << 4) + q * 4 + hi * 2;
    p[0] = __float2half(v.x); p[1] = __float2half(v.y);
    p[4] = __float2half(v.z); p[5] = __float2half(v.w);
}

// state-buffer half index for feature f, batch b
DEV_INLINE int st_hidx(int f, int b) {
    int kr = f >> 1;
    return (kr >> 3) * 512 + (kr & 3) * 128 + b * 4 + (((kr >> 2) & 1) << 1) + (f & 1);
}
// sequence-buffer half base for feature f (add n*4)
DEV_INLINE int seq_base(int f) {
    int kr = f >> 1;
    return (kr >> 3) * 131072 + (kr & 3) * 32768 + (((kr >> 2) & 1) << 1) + (f & 1);
}

// ---------------- setup ----------------
__global__ void k_setup(const float* __restrict__ emb, const float* __restrict__ Wih0,
                        const float* __restrict__ bih0, const float* __restrict__ bhh0,
                        const float* __restrict__ bih1, const float* __restrict__ bhh1,
                        const float* __restrict__ ebih, const float* __restrict__ ebhh) {
    int j = blockIdx.x * blockDim.x + threadIdx.x;
    if (j < 4096) {
        const float4* xr = (const float4*)(emb + E);               // BOS row
        const float4* wr = (const float4*)(Wih0 + (size_t)j * E);
        float s = 0.f;
#pragma unroll 4
        for (int k = 0; k < E / 4; k++) {
            float4 a = xr[k], w = wr[k];
            s += a.x * w.x + a.y * w.y + a.z * w.z + a.w * w.w;
        }
        g_gconst[j] = s + bih0[j] + bhh0[j];
        g_bsum1[j] = bih1[j] + bhh1[j];
    }
    if (j < 8192) g_encb[j] = ebih[j] + ebhh[j];
}

// ---------------- persistent decoder ----------------
// 128 blocks x 256 threads; block owns units [blk*8, blk*8+8) x 4 gates, both layers.
// interval k: layer0 computes h0(k) (k<T); layer1 computes h1(k-1) (k>=1).
__global__ void __launch_bounds__(256, 1) k_dec(const float* __restrict__ Whh0,
                                                const float* __restrict__ Wih1,
                                                const float* __restrict__ Whh1,
                                                const float* __restrict__ enc_h,
                                                const float* __restrict__ enc_c) {
    extern __shared__ __half sm[];
    __half* A0 = sm;                              // 32 x 1024 frag-packed (64KB each)
    __half* A1 = sm + 32768;
    __half* A2 = sm + 65536;
    __half* STG = sm + 98304;                     // 2 x 16KB staging
    float* gsm0 = (float*)STG;                    // aliases staging buffer 0
    float* gsm1 = gsm0 + 1056;
    volatile unsigned* s_go = (volatile unsigned*)(sm + 114688);  // past STG
    const uint32_t stg_b = (uint32_t)__cvta_generic_to_shared(STG);
    const int tid = threadIdx.x, lane = tid & 31, w = tid >> 5;
    const int u0 = blockIdx.x * 8;

    if (tid == 0) *s_go = 0;

    for (int i = tid; i < 8192; i += 256) {
        int s = i >> 8;
        int c = (i & 255) * 4;
        size_t grow = (size_t)((s >> 3) * 1024 + u0 + (s & 7));
        pack4(A0, 32, s, c, *(const float4*)(Whh0 + grow * 1024 + c));
        pack4(A1, 32, s, c, *(const float4*)(Wih1 + grow * 1024 + c));
        pack4(A2, 32, s, c, *(const float4*)(Whh1 + grow * 1024 + c));
    }

    const int u = w, b = lane, uu = u0 + u;
    const int hp = st_hidx(uu, b);
    const int xb = seq_base(uu);
    float c0 = enc_c[b * 1024 + uu];
    float c1 = enc_c[32768 + b * 1024 + uu];
    ((__half*)g_h0F[1])[hp] = __float2half(enc_h[b * 1024 + uu]);   // h(-1) -> buf 1
    ((__half*)g_h1F[1])[hp] = __float2half(enc_h[32768 + b * 1024 + uu]);
    const float gci = g_gconst[uu],        gcf = g_gconst[1024 + uu];
    const float gcg = g_gconst[2048 + uu], gco = g_gconst[3072 + uu];
    const float b1i = g_bsum1[uu],         b1f = g_bsum1[1024 + uu];
    const float b1g = g_bsum1[2048 + uu],  b1o = g_bsum1[3072 + uu];
    const int mt = w & 1, ntc = (w >> 1) * 8, r0 = mt * 16;
    const uint2* Au0 = (const uint2*)A0;
    const uint2* Au1 = (const uint2*)A1;
    const uint2* Au2 = (const uint2*)A2;

    grid_bar_dec(1, blockIdx.x, s_go);

    for (int k = 0; k <= T; k++) {
        const int pk = k & 1, pm1 = pk ^ 1;
        float a0c[4] = {0.f, 0.f, 0.f, 0.f};
        float a1c[4] = {0.f, 0.f, 0.f, 0.f};
        const uint2* h0src = g_h0F[pm1];
        const uint2* h1src = g_h1F[pk];
        const int cend = (k == 0) ? 4 : 8;

        stage_chunk(stg_b, h0src, tid); cp_commit();
        for (int c = 0; c < cend; c++) {
            // c==0: the lead sync is redundant (grid_bar's trailing __syncthreads
            // already ordered all warps past the previous epoch's buffer-1 reads)
            if (c) __syncthreads();
            if (c + 1 < cend) {
                const uint2* nsrc = (c + 1 < 4) ? h0src + (c + 1) * 2048
                                                : h1src + (c - 3) * 2048;
                stage_chunk(stg_b + ((c + 1) & 1) * 16384u, nsrc, tid);
                cp_commit();
                cp_wait<1>();
            } else {
                cp_wait<0>();
            }
            __syncthreads();
            const uint2* Bs = (const uint2*)(STG) + (c & 1) * 2048;
            if (c < 4) {
                // A offset for this chunk's 16 k-groups: c * 16 * (rstr*4=128) = c*2048
                const uint2* A0c = Au0 + (size_t)c * 2048;
                const uint2* A1c = Au1 + (size_t)c * 2048;
                if (k == 0)       gemm_sm1(A0c, 32, Bs, r0, ntc, lane, a0c);
                else if (k == T)  gemm_sm1(A1c, 32, Bs, r0, ntc, lane, a1c);
                else              gemm_sm2(A0c, A1c, 32, Bs, r0, ntc, lane, a0c, a1c);
            } else {
                const uint2* A2c = Au2 + (size_t)(c - 4) * 2048;
                gemm_sm1(A2c, 32, Bs, r0, ntc, lane, a1c);
            }
        }
        // no sync needed: gsm aliases staging buffer 0; final chunk GEMM (odd) read
        // buffer 1, and no cp.async targets buffer 0 here. frag_st slots warp-private.
        if (k < T)  frag_st(gsm0, r0, ntc, lane, a0c);
        if (k >= 1) frag_st(gsm1, r0, ntc, lane, a1c);
        __syncthreads();
        if (k < T) {
            float iv = gsm0[u * 33 + b] + gci;
            float fv = gsm0[(8 + u) * 33 + b] + gcf;
            float gv = gsm0[(16 + u) * 33 + b] + gcg;
            float ov = gsm0[(24 + u) * 33 + b] + gco;
            c0 = sigf(fv) * c0 + sigf(iv) * tanhff(gv);
            float h = sigf(ov) * tanhff(c0);
            ((__half*)g_h0F[pk])[hp] = __float2half(h);   // h0(k)
        }
        if (k >= 1) {
            float iv = gsm1[u * 33 + b] + b1i;
            float fv = gsm1[(8 + u) * 33 + b] + b1f;
            float gv = gsm1[(16 + u) * 33 + b] + b1g;
            float ov = gsm1[(24 + u) * 33 + b] + b1o;
            c1 = sigf(fv) * c1 + sigf(iv) * tanhff(gv);
            float h = sigf(ov) * tanhff(c1);
            __half hh = __float2half(h);
            ((__half*)g_h1F[pm1])[hp] = hh;               // h1(k-1)
            ((__half*)g_X2F)[xb + ((k - 1) * 32 + b) * 4] = hh;
        }
        grid_bar_dec(2 + k, blockIdx.x, s_go);
    }
    grid_fini(128);
}

// ---------------- encoder input-projection GEMM: Z = X @ Wih^T + bias ----------------
// grid (32 j-blocks, 16 n-blocks of 512, 2 dirs): weight tile reused over 512 cols.
__global__ void __launch_bounds__(256, 1) k_z(int l, const float* __restrict__ eWih) {
    extern __shared__ __half sm[];
    __half* As = sm;   // 64 x 1024 frag-packed (128KB)
    const int tid = threadIdx.x, lane = tid & 31, w = tid >> 5;
    const int jb = blockIdx.x * 64;
    const int n0 = blockIdx.y * 512;
    const int d = blockIdx.z;
    for (int i = tid; i < 16384; i += 256) {
        int s = i >> 8;
        int c = (i & 255) * 4;
        size_t grow = (size_t)(l * 2 + d) * 2048 + jb + s;
        pack4(As, 64, s, c, *(const float4*)(eWih + grow * 1024 + c));
    }
    __syncthreads();
    const uint2* Bf = l ? g_Y0F : g_X2F;
    const uint2* Au = (const uint2*)As;
    const int mt = w & 3;
    const int nh = (w >> 2) * 8;
    const int g = lane >> 2, q = lane & 3;
    float* Zp = g_Z + (size_t)d * 2048 * NSEQ;
    const float bias0 = g_encb[(l * 2 + d) * 2048 + jb + mt * 16 + g];
    const float bias1 = g_encb[(l * 2 + d) * 2048 + jb + mt * 16 + 8 + g];
    const int j0 = jb + mt * 16 + g;
    for (int ch = 0; ch < 32; ch++) {
        float acc[4] = {0.f, 0.f, 0.f, 0.f};
        gemm_g(Au, 64, 64, Bf, 8192, mt * 16, n0 + ch * 16 + nh, lane, acc);
        int n = n0 + ch * 16 + nh + 2 * q;
        Zp[(size_t)j0 * NSEQ + n]           = acc[0] + bias0;
        Zp[(size_t)j0 * NSEQ + n + 1]       = acc[1] + bias0;
        Zp[(size_t)(j0 + 8) * NSEQ + n]     = acc[2] + bias1;
        Zp[(size_t)(j0 + 8) * NSEQ + n + 1] = acc[3] + bias1;
    }
}

// ---------------- persistent encoder (64 blocks: 2 dirs x 32 blocks x 16 units) ------
// fwd and bwd use INDEPENDENT barrier domains; single-shot staging of the 32KB state;
// gsm in a DEDICATED smem region.
__global__ void __launch_bounds__(256, 1) k_enc(int l, const float* __restrict__ eWhh,
                                                float* __restrict__ out) {
    extern __shared__ __half sm[];
    __half* As = sm;                      // 64 x 512 frag-packed (64KB)
    __half* STG = sm + 32768;             // 2 x 16KB staging (whole state, one shot)
    float* gsm = (float*)(sm + 49152);    // dedicated 64 x 33 floats (8448B)
    volatile unsigned* s_go = (volatile unsigned*)(sm + 53376);
    const uint32_t stg_b = (uint32_t)__cvta_generic_to_shared(STG);
    const int tid = threadIdx.x, lane = tid & 31, w = tid >> 5;
    const int d = blockIdx.x >> 5;
    const int myblk = blockIdx.x & 31;
    const int u0 = myblk * 16;

    if (tid == 0) *s_go = 0;

    for (int i = tid; i < 8192; i += 256) {
        int s = i >> 7;            // 0..63 packed row: gate*16 + ulocal
        int c = (i & 127) * 4;
        size_t grow = (size_t)(l * 2 + d) * 2048 + (s >> 4) * 512 + u0 + (s & 15);
        pack4(As, 64, s, c, *(const float4*)(eWhh + grow * 512 + c));
    }

    const int mt = w & 3, r0 = mt * 16;
    const int nh = (w >> 2) * 16;
    float cst[2] = {0.f, 0.f};
    const float* Zp = g_Z + (size_t)d * 2048 * NSEQ;
    const uint2* Au = (const uint2*)As;
    __syncthreads();

    for (int s = 0; s < T; s++) {
        const int p = s & 1;
        const int tau = d ? (T - 1 - s) : s;
        // issue state staging FIRST (fire-and-forget), so it overlaps Z prefetch
        if (s) {
            const uint2* hsrc = g_ehF[d][1 - p];
            stage_chunk(stg_b, hsrc, tid);
            stage_chunk(stg_b + 16384u, hsrc + 2048, tid);
            cp_commit();
        }
        // prefetch Z for this thread's two (u,b) pairs (overlaps the cp.async burst)
        float z[2][4];
#pragma unroll
        for (int e = 0; e < 2; e++) {
            int idx = e * 256 + tid;
            int uu2 = u0 + (idx >> 5), b2 = idx & 31;
            int n2 = tau * 32 + b2;
            z[e][0] = Zp[(size_t)uu2 * NSEQ + n2];
            z[e][1] = Zp[(size_t)(512 + uu2) * NSEQ + n2];
            z[e][2] = Zp[(size_t)(1024 + uu2) * NSEQ + n2];
            z[e][3] = Zp[(size_t)(1536 + uu2) * NSEQ + n2];
        }
        float acc0[4] = {0.f, 0.f, 0.f, 0.f};
        float acc1[4] = {0.f, 0.f, 0.f, 0.f};
        if (s) {
            cp_wait<0>();
            __syncthreads();
            const uint2* Bs = (const uint2*)STG;
            gemm_sm2n(Au,        64, Bs,        r0, nh, lane, acc0, acc1);
            gemm_sm2n(Au + 4096, 64, Bs + 2048, r0, nh, lane, acc0, acc1);
        }
        // gsm is dedicated: frag_st can proceed without a pre-sync
        frag_st(gsm, r0, nh, lane, acc0);
        frag_st(gsm, r0, nh + 8, lane, acc1);
        __syncthreads();
#pragma unroll
        for (int e = 0; e < 2; e++) {
            int idx = e * 256 + tid;
            int ul = idx >> 5, b2 = idx & 31;
            int uu2 = u0 + ul;
            int n2 = tau * 32 + b2;
            float iv = gsm[ul * 33 + b2] + z[e][0];
            float fv = gsm[(16 + ul) * 33 + b2] + z[e][1];
            float gv = gsm[(32 + ul) * 33 + b2] + z[e][2];
            float ov = gsm[(48 + ul) * 33 + b2] + z[e][3];
            cst[e] = sigf(fv) * cst[e] + sigf(iv) * tanhff(gv);
            float h = sigf(ov) * tanhff(cst[e]);
            __half hh = __float2half(h);
            ((__half*)g_ehF[d][p])[st_hidx(uu2, b2)] = hh;   // h(s)
            int f = d * 512 + uu2;
            if (l == 0) {
                ((__half*)g_Y0F)[seq_base(f) + n2 * 4] = hh;
            } else {
                out[(size_t)b2 * (T * HD) + (size_t)tau * HD + f] = h;
                if (s == T - 1) {
                    out[OUT_OFF_H + b2 * HD + f] = h;
                    out[OUT_OFF_H + 32768 + b2 * HD + f] = h;
                    out[OUT_OFF_C + b2 * HD + f] = cst[e];
                    out[OUT_OFF_C + 32768 + b2 * HD + f] = cst[e];
                }
            }
        }
        grid_bar(s + 1, d * 32, 32, myblk, s_go);
    }
    grid_fini(64);
}

// ---------------- host launcher ----------------
extern "C" void kernel_launch(void* const* d_in, const int* in_sizes, int n_in,
                              void* d_out, int out_size) {
    (void)in_sizes; (void)n_in; (void)out_size;
    const float* enc_h = (const float*)d_in[1];
    const float* enc_c = (const float*)d_in[2];
    const float* emb   = (const float*)d_in[4];
    const float* Wih0  = (const float*)d_in[5];
    const float* Whh0  = (const float*)d_in[6];
    const float* bih0  = (const float*)d_in[7];
    const float* bhh0  = (const float*)d_in[8];
    const float* Wih1  = (const float*)d_in[9];
    const float* Whh1  = (const float*)d_in[10];
    const float* bih1  = (const float*)d_in[11];
    const float* bhh1  = (const float*)d_in[12];
    const float* eWih  = (const float*)d_in[13];
    const float* eWhh  = (const float*)d_in[14];
    const float* ebih  = (const float*)d_in[15];
    const float* ebhh  = (const float*)d_in[16];
    float* out = (float*)d_out;

    cudaFuncSetAttribute(k_dec, cudaFuncAttributeMaxDynamicSharedMemorySize, 229504);
    cudaFuncSetAttribute(k_z,   cudaFuncAttributeMaxDynamicSharedMemorySize, 131072);
    cudaFuncSetAttribute(k_enc, cudaFuncAttributeMaxDynamicSharedMemorySize, 107008);

    k_setup<<<32, 256>>>(emb, Wih0, bih0, bhh0, bih1, bhh1, ebih, ebhh);
    k_dec<<<128, 256, 229504>>>(Whh0, Wih1, Whh1, enc_h, enc_c);
    for (int l = 0; l < 2; l++) {
        k_z<<<dim3(32, 16, 2), 256, 131072>>>(l, eWih);
        k_enc<<<64, 256, 107008>>>(l, eWhh, out);
    }
}